// round 14
// baseline (speedup 1.0000x reference)
#include <cuda_runtime.h>
#include <cuda_fp16.h>
#include <cstdint>
#include <math.h>

// Problem constants
#define BB   8
#define HH   128
#define WW   128
#define CIN  64
#define GG   2
#define GCH  32      // channels per group
#define SCH  288     // K*K*GC
#define GF   64      // filters per group
#define NP   (BB*HH*WW)   // 131072 pixels

// Scratch
__device__ __half g_samp16[(size_t)GG * NP * SCH]; // sampled field (151 MB)
__device__ float  g_off [(size_t)GG * NP * 18];    // offsets       (19 MB)
__device__ float  g_pww [(size_t)GG * SCH * GF];   // tf32-rounded pw weights

// ---------------------------------------------------------------------------
// helpers
// ---------------------------------------------------------------------------
__device__ __forceinline__ void cpa16(void* s, const void* gsrc, bool v) {
    unsigned int sa = (unsigned int)__cvta_generic_to_shared(s);
    asm volatile("cp.async.cg.shared.global [%0], [%1], 16, %2;"
                 :: "r"(sa), "l"(gsrc), "r"(v ? 16u : 0u));
}
#define CPA_COMMIT() asm volatile("cp.async.commit_group;")
#define CPA_WAIT0()  asm volatile("cp.async.wait_group 0;")

__device__ __forceinline__ float to_tf32(float x) {
    unsigned int u;
    asm("cvt.rna.tf32.f32 %0, %1;" : "=r"(u) : "f"(x));
    return __uint_as_float(u);
}

__device__ __forceinline__ void mma_tf32(float* d,
    unsigned int a0, unsigned int a1, unsigned int a2, unsigned int a3,
    unsigned int b0, unsigned int b1)
{
    asm volatile(
        "mma.sync.aligned.m16n8k8.row.col.f32.tf32.tf32.f32 "
        "{%0,%1,%2,%3}, {%4,%5,%6,%7}, {%8,%9}, {%0,%1,%2,%3};"
        : "+f"(d[0]), "+f"(d[1]), "+f"(d[2]), "+f"(d[3])
        : "r"(a0), "r"(a1), "r"(a2), "r"(a3), "r"(b0), "r"(b1));
}

// ===========================================================================
// Kernel P: pre-round pw weights to tf32 (once, tiny)
// ===========================================================================
__global__ void k_prep(const float* __restrict__ pw_w) {
    int i = blockIdx.x * 256 + threadIdx.x;
    if (i < GG * SCH * GF) g_pww[i] = to_tf32(pw_w[i]);
}

// ===========================================================================
// Kernel 0: offset conv (3x3, 32 -> 18) per group. (validated round-8 FFMA)
// 32x16 pixel tile, 256 threads, 2 pixels per thread.
// ===========================================================================
#define OHP_W 34
#define OHP_H 18
#define XTS   17
#define XT_F  (OHP_H*OHP_W*XTS)
#define WS_F  5760
#define OFF_SMEM_BYTES ((XT_F + WS_F + 32) * 4)

__global__ __launch_bounds__(256) void k_offsets(
    const float* __restrict__ x,
    const float* __restrict__ off_w,
    const float* __restrict__ off_b)
{
    extern __shared__ float sm0[];
    float* xt   = sm0;
    float* ws   = sm0 + XT_F;
    float* wb   = sm0 + XT_F + WS_F;
    float* soff = sm0;

    const int tid = threadIdx.x;
    const int z   = blockIdx.z;
    const int g   = z & 1;
    const int b   = z >> 1;
    const int ty0 = blockIdx.y * 16;
    const int tx0 = blockIdx.x * 32;

    for (int i = tid; i < WS_F; i += 256) {
        int r = i / 20, j = i % 20;
        ws[i] = (j < 18) ? off_w[(size_t)(g * 288 + r) * 18 + j] : 0.f;
    }
    if (tid < 18) wb[tid] = off_b[g * 18 + tid];

    const int px  = tid & 31;
    const int py0 = tid >> 5;

    float acc[2][18];
#pragma unroll
    for (int pp = 0; pp < 2; pp++)
#pragma unroll
        for (int j = 0; j < 18; j++) acc[pp][j] = 0.f;

    for (int cch = 0; cch < 2; cch++) {
        __syncthreads();
        for (int i = tid; i < OHP_H * OHP_W * 16; i += 256) {
            int pos = i >> 4, c = i & 15;
            int hy = ty0 + pos / OHP_W - 1, hx = tx0 + pos % OHP_W - 1;
            float v = 0.f;
            if (hy >= 0 && hy < HH && hx >= 0 && hx < WW)
                v = x[((size_t)((b * HH + hy) * WW + hx)) * CIN
                      + g * GCH + cch * 16 + c];
            xt[pos * XTS + c] = v;
        }
        __syncthreads();

#pragma unroll 1
        for (int t = 0; t < 9; t++) {
            const int dy = t / 3, dx = t % 3;
            const float* wt = &ws[(t * 32 + cch * 16) * 20];
            const int base = (dy * OHP_W + px + dx) * XTS;
#pragma unroll 2
            for (int c = 0; c < 16; c++) {
                float v0 = xt[base + ((py0    ) * OHP_W) * XTS + c];
                float v1 = xt[base + ((py0 + 8) * OHP_W) * XTS + c];
                const float4* wv = (const float4*)&wt[c * 20];
                float4 w0 = wv[0], w1 = wv[1], w2 = wv[2], w3 = wv[3];
                float2 w4 = *(const float2*)&wt[c * 20 + 16];
#pragma unroll
                for (int pp = 0; pp < 2; pp++) {
                    float v = pp == 0 ? v0 : v1;
                    acc[pp][ 0] = fmaf(v, w0.x, acc[pp][ 0]);
                    acc[pp][ 1] = fmaf(v, w0.y, acc[pp][ 1]);
                    acc[pp][ 2] = fmaf(v, w0.z, acc[pp][ 2]);
                    acc[pp][ 3] = fmaf(v, w0.w, acc[pp][ 3]);
                    acc[pp][ 4] = fmaf(v, w1.x, acc[pp][ 4]);
                    acc[pp][ 5] = fmaf(v, w1.y, acc[pp][ 5]);
                    acc[pp][ 6] = fmaf(v, w1.z, acc[pp][ 6]);
                    acc[pp][ 7] = fmaf(v, w1.w, acc[pp][ 7]);
                    acc[pp][ 8] = fmaf(v, w2.x, acc[pp][ 8]);
                    acc[pp][ 9] = fmaf(v, w2.y, acc[pp][ 9]);
                    acc[pp][10] = fmaf(v, w2.z, acc[pp][10]);
                    acc[pp][11] = fmaf(v, w2.w, acc[pp][11]);
                    acc[pp][12] = fmaf(v, w3.x, acc[pp][12]);
                    acc[pp][13] = fmaf(v, w3.y, acc[pp][13]);
                    acc[pp][14] = fmaf(v, w3.z, acc[pp][14]);
                    acc[pp][15] = fmaf(v, w3.w, acc[pp][15]);
                    acc[pp][16] = fmaf(v, w4.x, acc[pp][16]);
                    acc[pp][17] = fmaf(v, w4.y, acc[pp][17]);
                }
            }
        }
    }
    __syncthreads();

#pragma unroll
    for (int pp = 0; pp < 2; pp++) {
        const int p = (py0 + pp * 8) * 32 + px;
#pragma unroll
        for (int j = 0; j < 18; j++)
            soff[p * 18 + j] = acc[pp][j] + wb[j];
    }
    __syncthreads();

    const size_t pbase = (size_t)b * (HH * WW) + (size_t)ty0 * WW + tx0;
    for (int i = tid; i < 32 * 16 * 18; i += 256) {
        int row = i / 576, rem = i % 576;
        g_off[((size_t)g * NP + pbase + (size_t)row * WW) * 18 + rem] = soff[i];
    }
}

// ===========================================================================
// Kernel 1: bilinear sampling, SMEM-TILED. 16x16 px tile per (b,g), 256 thr.
// x window [tile-5, tile+20] (26x26x32 fp32, 86.5KB) staged once; gathers hit
// LDS (29cyc) instead of L2 (~250cyc). Rare out-of-window taps fall back to
// identical global loads -> bit-identical results.
// ===========================================================================
#define TS    16
#define SHLO  5
#define SWIN  26
#define XS_F  (SWIN * SWIN * 32)
#define SAMP_SMEM_BYTES (XS_F * 4)    // 86528 B -> 2 blocks/SM

__global__ __launch_bounds__(256) void k_sample(
    const float* __restrict__ x)      // [B,H,W,64]
{
    extern __shared__ float xs[];
    const int tid = threadIdx.x;
    const int z   = blockIdx.z;
    const int g   = z & 1;
    const int b   = z >> 1;
    const int ty0 = blockIdx.y * TS;
    const int tx0 = blockIdx.x * TS;

    // stage x window (fp32, exact copies; OOB zero-filled but never read)
    for (int i = tid; i < SWIN * SWIN * 8; i += 256) {
        int pos = i >> 3, q = i & 7;
        int gy = ty0 - SHLO + pos / SWIN;
        int gx = tx0 - SHLO + pos % SWIN;
        bool ok = (gy >= 0 && gy < HH && gx >= 0 && gx < WW);
        const float* src = ok
            ? &x[((size_t)((b * HH + gy) * WW + gx)) * CIN + g * GCH + q * 4]
            : x;
        cpa16(&xs[pos * 32 + q * 4], src, ok);
    }
    CPA_COMMIT();
    CPA_WAIT0();
    __syncthreads();

    const int warp = tid >> 5, lane = tid & 31;
    const float* xg = x + (size_t)b * (HH * WW) * CIN + g * GCH + lane;

    for (int wp = 0; wp < 32; wp++) {
        const int pl = warp * 32 + wp;          // 0..255
        const int py = pl >> 4, px = pl & 15;
        const int gy = ty0 + py, gx = tx0 + px;
        const int p  = b * 16384 + gy * WW + gx;

        float offv = 0.f;
        if (lane < 18) offv = g_off[((size_t)g * NP + p) * 18 + lane];
        __half* outp = &g_samp16[((size_t)g * NP + p) * SCH + lane];

#pragma unroll
        for (int k = 0; k < 9; k++) {
            float ox = __shfl_sync(0xffffffffu, offv, 2 * k);
            float oy = __shfl_sync(0xffffffffu, offv, 2 * k + 1);
            float lx = (float)gx + (float)(k % 3 - 1) + ox;
            float ly = (float)gy + (float)(k / 3 - 1) + oy;
            lx = fminf(fmaxf(lx, 0.f), 127.f);
            ly = fminf(fmaxf(ly, 0.f), 127.f);
            float x0f = fminf(fmaxf(floorf(lx), 0.f), 127.f);
            float y0f = fminf(fmaxf(floorf(ly), 0.f), 127.f);
            float x1f = fminf(x0f + 1.f, 127.f);
            float y1f = fminf(y0f + 1.f, 127.f);
            int x0 = (int)x0f, x1 = (int)x1f, y0 = (int)y0f, y1 = (int)y1f;
            float dx1 = x1f - lx, dx0 = lx - x0f;
            float dy1 = y1f - ly, dy0 = ly - y0f;
            float wa = dx1 * dy1, wbv = dx1 * dy0;
            float wc = dx0 * dy1, wd = dx0 * dy0;

            int wx0 = x0 - (tx0 - SHLO), wy0 = y0 - (ty0 - SHLO);
            int wx1 = x1 - (tx0 - SHLO), wy1 = y1 - (ty0 - SHLO);
            float Ia, Ib, Ic, Id;
            if (wx0 >= 0 && wy0 >= 0 && wx1 < SWIN && wy1 < SWIN) {
                Ia = xs[(wy0 * SWIN + wx0) * 32 + lane];
                Ib = xs[(wy1 * SWIN + wx0) * 32 + lane];
                Ic = xs[(wy0 * SWIN + wx1) * 32 + lane];
                Id = xs[(wy1 * SWIN + wx1) * 32 + lane];
            } else {
                Ia = __ldg(xg + (size_t)(y0 * WW + x0) * CIN);
                Ib = __ldg(xg + (size_t)(y1 * WW + x0) * CIN);
                Ic = __ldg(xg + (size_t)(y0 * WW + x1) * CIN);
                Id = __ldg(xg + (size_t)(y1 * WW + x1) * CIN);
            }
            outp[k * 32] = __float2half_rn(wa*Ia + wbv*Ib + wc*Ic + wd*Id);
        }
    }
}

// ===========================================================================
// Kernel 2: fused depthwise(3x3) + pointwise(288->64, tf32 mma).
// Validated round-10/13 version (225.6us, rel_err 3.58e-4).
// ===========================================================================
#define CHUNK  96
#define SM_HALO_H (100 * CHUNK)
#define SM_HALO_F (SM_HALO_H / 2)
#define SM_Y    (64 * 100)
#define SM_PW   (96 * 72)
#define SM_DW   (9 * CHUNK)
#define SM_BASE 200
#define SM_BYTES ((SM_HALO_F + SM_Y + SM_PW + SM_DW + SM_BASE + 8) * 4)
#define OUTP    68

__global__ __launch_bounds__(512, 2) void k_dwpw(
    const float* __restrict__ dw_w,
    const float* __restrict__ dw_b,
    const float* __restrict__ pw_b,
    float* __restrict__ out)
{
    extern __shared__ float smem[];
    __half* s_hal = (__half*)smem;
    float* s_y    = smem + SM_HALO_F;
    float* s_pw   = smem + SM_HALO_F + SM_Y;
    float* s_dw   = smem + SM_HALO_F + SM_Y + SM_PW;
    const __half** s_base =
        (const __half**)(smem + SM_HALO_F + SM_Y + SM_PW + SM_DW + 8);
    float* s_red  = s_pw;
    float* s_out  = smem;

    const int tid = threadIdx.x;
    const int z   = blockIdx.z;
    const int gg  = z & 1;
    const int b   = z >> 1;
    const int ty0 = blockIdx.y * 8;
    const int tx0 = blockIdx.x * 8;

    const int warp = tid >> 5, lane = tid & 31;
    const int lg   = lane >> 2;
    const int lt   = lane & 3;
    const int team = warp >> 3;
    const int mtb  = (warp & 3) * 16;
    const int ntb  = ((warp >> 2) & 1) * 32;

    float acc[4][4];
#pragma unroll
    for (int j = 0; j < 4; j++)
#pragma unroll
        for (int q = 0; q < 4; q++) acc[j][q] = 0.f;

    float4* d4 = (float4*)s_dw;

    if (tid < 100) {
        int hy = ty0 + tid / 10 - 1, hx = tx0 + tid % 10 - 1;
        bool ok = (hy >= 0 && hy < HH && hx >= 0 && hx < WW);
        s_base[tid] = ok
            ? &g_samp16[((size_t)gg * NP + (size_t)((b * HH + hy) * WW + hx)) * SCH]
            : (const __half*)0;
    }
    __syncthreads();

    auto stage_halo = [&](int cc) {
        const int cbase = cc * CHUNK;
        if (lane < 12) {
            for (int hp = warp; hp < 100; hp += 16) {
                const __half* base = s_base[hp];
                bool ok = (base != 0);
                const void* src = ok ? (const void*)(base + cbase + lane * 8)
                                     : (const void*)g_samp16;
                cpa16(&s_hal[hp * CHUNK + lane * 8], src, ok);
            }
        }
    };

    stage_halo(0);
    CPA_COMMIT();

    for (int cc = 0; cc < 3; cc++) {
        const int cbase = cc * CHUNK;
        __syncthreads();

        for (int i = tid; i < 9 * 24; i += 512) {
            int t = i / 24, c4 = i % 24;
            cpa16(&s_dw[i * 4],
                  &dw_w[(size_t)gg * 2592 + t * SCH + cbase + c4 * 4], true);
        }
        for (int i = tid; i < 96 * 16; i += 512) {
            int c = i >> 4, f4 = i & 15;
            cpa16(&s_pw[c * 72 + f4 * 4],
                  &g_pww[((size_t)gg * SCH + cbase + c) * 64 + f4 * 4], true);
        }
        CPA_COMMIT();
        CPA_WAIT0();
        __syncthreads();

        if (tid < 384) {
            const int strip = tid / 24, c4 = tid % 24;
            const int py = strip >> 1, qx0 = (strip & 1) * 4;
            float4 bias = __ldg((const float4*)&dw_b[gg * SCH + cbase + c4 * 4]);
            float a[4][4];
#pragma unroll
            for (int oxp = 0; oxp < 4; oxp++) {
                a[oxp][0] = bias.x; a[oxp][1] = bias.y;
                a[oxp][2] = bias.z; a[oxp][3] = bias.w;
            }
#pragma unroll
            for (int ty = 0; ty < 3; ty++) {
                const __half* hrow = &s_hal[((py + ty) * 10 + qx0) * CHUNK + c4 * 4];
                float vv[6][4];
#pragma unroll
                for (int i = 0; i < 6; i++) {
                    uint2 u = *(const uint2*)&hrow[i * CHUNK];
                    float2 f01 = __half22float2(*(__half2*)&u.x);
                    float2 f23 = __half22float2(*(__half2*)&u.y);
                    vv[i][0] = f01.x; vv[i][1] = f01.y;
                    vv[i][2] = f23.x; vv[i][3] = f23.y;
                }
#pragma unroll
                for (int tx = 0; tx < 3; tx++) {
                    float4 w = d4[(ty * 3 + tx) * 24 + c4];
#pragma unroll
                    for (int oxp = 0; oxp < 4; oxp++) {
                        a[oxp][0] = fmaf(w.x, vv[oxp + tx][0], a[oxp][0]);
                        a[oxp][1] = fmaf(w.y, vv[oxp + tx][1], a[oxp][1]);
                        a[oxp][2] = fmaf(w.z, vv[oxp + tx][2], a[oxp][2]);
                        a[oxp][3] = fmaf(w.w, vv[oxp + tx][3], a[oxp][3]);
                    }
                }
            }
#pragma unroll
            for (int oxp = 0; oxp < 4; oxp++) {
                float4 r = make_float4(to_tf32(a[oxp][0]), to_tf32(a[oxp][1]),
                                       to_tf32(a[oxp][2]), to_tf32(a[oxp][3]));
                *(float4*)&s_y[(py * 8 + qx0 + oxp) * 100 + c4 * 4] = r;
            }
        }
        __syncthreads();

        if (cc < 2) {
            stage_halo(cc + 1);
            CPA_COMMIT();
        }

#pragma unroll
        for (int s = 0; s < 6; s++) {
            const int k0 = team * 48 + s * 8;
            const unsigned int* yA =
                (const unsigned int*)&s_y[(mtb + lg) * 100 + k0 + lt];
            unsigned int a0 = yA[0],   a1 = yA[800];
            unsigned int a2 = yA[4],   a3 = yA[804];
#pragma unroll
            for (int j = 0; j < 4; j++) {
                unsigned int b0 = *(const unsigned int*)
                    &s_pw[(k0 + lt    ) * 72 + ntb + j * 8 + lg];
                unsigned int b1 = *(const unsigned int*)
                    &s_pw[(k0 + lt + 4) * 72 + ntb + j * 8 + lg];
                mma_tf32(acc[j], a0, a1, a2, a3, b0, b1);
            }
        }
    }
    __syncthreads();

    if (team == 1) {
        float* dst = &s_red[((warp & 7) * 32 + lane) * 16];
#pragma unroll
        for (int j = 0; j < 4; j++)
#pragma unroll
            for (int q = 0; q < 4; q++) dst[j * 4 + q] = acc[j][q];
    }
    __syncthreads();
    if (team == 0) {
        const float* src = &s_red[((warp & 7) * 32 + lane) * 16];
        const int px0 = mtb + lg, px1 = mtb + lg + 8;
#pragma unroll
        for (int j = 0; j < 4; j++) {
            int f0 = ntb + j * 8 + 2 * lt;
            float b0v = __ldg(&pw_b[gg * GF + f0]);
            float b1v = __ldg(&pw_b[gg * GF + f0 + 1]);
            s_out[px0 * OUTP + f0]     = acc[j][0] + src[j*4+0] + b0v;
            s_out[px0 * OUTP + f0 + 1] = acc[j][1] + src[j*4+1] + b1v;
            s_out[px1 * OUTP + f0]     = acc[j][2] + src[j*4+2] + b0v;
            s_out[px1 * OUTP + f0 + 1] = acc[j][3] + src[j*4+3] + b1v;
        }
    }
    __syncthreads();

    for (int i = tid; i < 4096; i += 512) {
        int p = i >> 6, f = i & 63;
        int py = p >> 3, px = p & 7;
        out[((size_t)((b * HH + ty0 + py) * WW) + tx0 + px) * (GG * GF)
            + gg * GF + f] = s_out[p * OUTP + f];
    }
}

// ---------------------------------------------------------------------------
extern "C" void kernel_launch(void* const* d_in, const int* in_sizes, int n_in,
                              void* d_out, int out_size)
{
    const float* x     = (const float*)d_in[0];
    const float* off_w = (const float*)d_in[1];
    const float* off_b = (const float*)d_in[2];
    const float* dw_w  = (const float*)d_in[3];
    const float* dw_b  = (const float*)d_in[4];
    const float* pw_w  = (const float*)d_in[5];
    const float* pw_b  = (const float*)d_in[6];
    float* out = (float*)d_out;

    cudaFuncSetAttribute(k_offsets, cudaFuncAttributeMaxDynamicSharedMemorySize,
                         OFF_SMEM_BYTES);
    cudaFuncSetAttribute(k_sample, cudaFuncAttributeMaxDynamicSharedMemorySize,
                         SAMP_SMEM_BYTES);
    cudaFuncSetAttribute(k_dwpw, cudaFuncAttributeMaxDynamicSharedMemorySize,
                         SM_BYTES);

    k_prep<<<(GG * SCH * GF + 255) / 256, 256>>>(pw_w);
    k_offsets<<<dim3(WW/32, HH/16, BB*GG), 256, OFF_SMEM_BYTES>>>(x, off_w, off_b);
    k_sample<<<dim3(WW/TS, HH/TS, BB*GG), 256, SAMP_SMEM_BYTES>>>(x);
    k_dwpw<<<dim3(WW / 8, HH / 8, BB * GG), 512, SM_BYTES>>>(
        dw_w, dw_b, pw_b, out);
}

// round 15
// speedup vs baseline: 1.1374x; 1.1374x over previous
#include <cuda_runtime.h>
#include <cuda_fp16.h>
#include <cstdint>
#include <math.h>

// Problem constants
#define BB   8
#define HH   128
#define WW   128
#define CIN  64
#define GG   2
#define GCH  32      // channels per group
#define SCH  288     // K*K*GC
#define GF   64      // filters per group
#define NP   (BB*HH*WW)   // 131072 pixels

// Scratch
__device__ __half g_samp16[(size_t)GG * NP * SCH]; // sampled field (151 MB)
__device__ float  g_off [(size_t)GG * NP * 18];    // offsets       (19 MB)
__device__ float  g_pww [(size_t)GG * SCH * GF];   // tf32-rounded pw weights

// ---------------------------------------------------------------------------
// helpers
// ---------------------------------------------------------------------------
__device__ __forceinline__ void cpa16(void* s, const void* gsrc, bool v) {
    unsigned int sa = (unsigned int)__cvta_generic_to_shared(s);
    asm volatile("cp.async.cg.shared.global [%0], [%1], 16, %2;"
                 :: "r"(sa), "l"(gsrc), "r"(v ? 16u : 0u));
}
#define CPA_COMMIT() asm volatile("cp.async.commit_group;")
#define CPA_WAIT0()  asm volatile("cp.async.wait_group 0;")

__device__ __forceinline__ float to_tf32(float x) {
    unsigned int u;
    asm("cvt.rna.tf32.f32 %0, %1;" : "=r"(u) : "f"(x));
    return __uint_as_float(u);
}

__device__ __forceinline__ void mma_tf32(float* d,
    unsigned int a0, unsigned int a1, unsigned int a2, unsigned int a3,
    unsigned int b0, unsigned int b1)
{
    asm volatile(
        "mma.sync.aligned.m16n8k8.row.col.f32.tf32.tf32.f32 "
        "{%0,%1,%2,%3}, {%4,%5,%6,%7}, {%8,%9}, {%0,%1,%2,%3};"
        : "+f"(d[0]), "+f"(d[1]), "+f"(d[2]), "+f"(d[3])
        : "r"(a0), "r"(a1), "r"(a2), "r"(a3), "r"(b0), "r"(b1));
}

// ===========================================================================
// Kernel P: pre-round pw weights to tf32 (once, tiny)
// ===========================================================================
__global__ void k_prep(const float* __restrict__ pw_w) {
    int i = blockIdx.x * 256 + threadIdx.x;
    if (i < GG * SCH * GF) g_pww[i] = to_tf32(pw_w[i]);
}

// ===========================================================================
// Kernel 0: offset conv (3x3, 32 -> 18) per group. (validated round-8 FFMA)
// 32x16 pixel tile, 256 threads, 2 pixels per thread.
// ===========================================================================
#define OHP_W 34
#define OHP_H 18
#define XTS   17
#define XT_F  (OHP_H*OHP_W*XTS)
#define WS_F  5760
#define OFF_SMEM_BYTES ((XT_F + WS_F + 32) * 4)

__global__ __launch_bounds__(256) void k_offsets(
    const float* __restrict__ x,
    const float* __restrict__ off_w,
    const float* __restrict__ off_b)
{
    extern __shared__ float sm0[];
    float* xt   = sm0;
    float* ws   = sm0 + XT_F;
    float* wb   = sm0 + XT_F + WS_F;
    float* soff = sm0;

    const int tid = threadIdx.x;
    const int z   = blockIdx.z;
    const int g   = z & 1;
    const int b   = z >> 1;
    const int ty0 = blockIdx.y * 16;
    const int tx0 = blockIdx.x * 32;

    for (int i = tid; i < WS_F; i += 256) {
        int r = i / 20, j = i % 20;
        ws[i] = (j < 18) ? off_w[(size_t)(g * 288 + r) * 18 + j] : 0.f;
    }
    if (tid < 18) wb[tid] = off_b[g * 18 + tid];

    const int px  = tid & 31;
    const int py0 = tid >> 5;

    float acc[2][18];
#pragma unroll
    for (int pp = 0; pp < 2; pp++)
#pragma unroll
        for (int j = 0; j < 18; j++) acc[pp][j] = 0.f;

    for (int cch = 0; cch < 2; cch++) {
        __syncthreads();
        for (int i = tid; i < OHP_H * OHP_W * 16; i += 256) {
            int pos = i >> 4, c = i & 15;
            int hy = ty0 + pos / OHP_W - 1, hx = tx0 + pos % OHP_W - 1;
            float v = 0.f;
            if (hy >= 0 && hy < HH && hx >= 0 && hx < WW)
                v = x[((size_t)((b * HH + hy) * WW + hx)) * CIN
                      + g * GCH + cch * 16 + c];
            xt[pos * XTS + c] = v;
        }
        __syncthreads();

#pragma unroll 1
        for (int t = 0; t < 9; t++) {
            const int dy = t / 3, dx = t % 3;
            const float* wt = &ws[(t * 32 + cch * 16) * 20];
            const int base = (dy * OHP_W + px + dx) * XTS;
#pragma unroll 2
            for (int c = 0; c < 16; c++) {
                float v0 = xt[base + ((py0    ) * OHP_W) * XTS + c];
                float v1 = xt[base + ((py0 + 8) * OHP_W) * XTS + c];
                const float4* wv = (const float4*)&wt[c * 20];
                float4 w0 = wv[0], w1 = wv[1], w2 = wv[2], w3 = wv[3];
                float2 w4 = *(const float2*)&wt[c * 20 + 16];
#pragma unroll
                for (int pp = 0; pp < 2; pp++) {
                    float v = pp == 0 ? v0 : v1;
                    acc[pp][ 0] = fmaf(v, w0.x, acc[pp][ 0]);
                    acc[pp][ 1] = fmaf(v, w0.y, acc[pp][ 1]);
                    acc[pp][ 2] = fmaf(v, w0.z, acc[pp][ 2]);
                    acc[pp][ 3] = fmaf(v, w0.w, acc[pp][ 3]);
                    acc[pp][ 4] = fmaf(v, w1.x, acc[pp][ 4]);
                    acc[pp][ 5] = fmaf(v, w1.y, acc[pp][ 5]);
                    acc[pp][ 6] = fmaf(v, w1.z, acc[pp][ 6]);
                    acc[pp][ 7] = fmaf(v, w1.w, acc[pp][ 7]);
                    acc[pp][ 8] = fmaf(v, w2.x, acc[pp][ 8]);
                    acc[pp][ 9] = fmaf(v, w2.y, acc[pp][ 9]);
                    acc[pp][10] = fmaf(v, w2.z, acc[pp][10]);
                    acc[pp][11] = fmaf(v, w2.w, acc[pp][11]);
                    acc[pp][12] = fmaf(v, w3.x, acc[pp][12]);
                    acc[pp][13] = fmaf(v, w3.y, acc[pp][13]);
                    acc[pp][14] = fmaf(v, w3.z, acc[pp][14]);
                    acc[pp][15] = fmaf(v, w3.w, acc[pp][15]);
                    acc[pp][16] = fmaf(v, w4.x, acc[pp][16]);
                    acc[pp][17] = fmaf(v, w4.y, acc[pp][17]);
                }
            }
        }
    }
    __syncthreads();

#pragma unroll
    for (int pp = 0; pp < 2; pp++) {
        const int p = (py0 + pp * 8) * 32 + px;
#pragma unroll
        for (int j = 0; j < 18; j++)
            soff[p * 18 + j] = acc[pp][j] + wb[j];
    }
    __syncthreads();

    const size_t pbase = (size_t)b * (HH * WW) + (size_t)ty0 * WW + tx0;
    for (int i = tid; i < 32 * 16 * 18; i += 256) {
        int row = i / 576, rem = i % 576;
        g_off[((size_t)g * NP + pbase + (size_t)row * WW) * 18 + rem] = soff[i];
    }
}

// ===========================================================================
// Kernel 1: bilinear sampling. One warp per (pixel, group). lane = channel.
// FULL 9-tap batching: all 36 gather addresses + weights computed first,
// then 36 independent gathers in flight (MLP 36), then combines.
// Per-tap arithmetic identical to the validated version.
// ===========================================================================
__global__ __launch_bounds__(256) void k_sample(
    const float* __restrict__ x)
{
    const int tid  = threadIdx.x;
    const int g    = blockIdx.y;
    const int warp = tid >> 5, lane = tid & 31;
    const int p   = blockIdx.x * 8 + warp;
    const int b   = p >> 14;
    const int rem = p & 16383;
    const int yy  = rem >> 7;
    const int xx  = rem & 127;

    float offv = 0.f;
    if (lane < 18) offv = g_off[((size_t)g * NP + p) * 18 + lane];

    const float* xg = x + (size_t)b * (HH * WW) * CIN + g * GCH + lane;
    __half* outp = &g_samp16[((size_t)g * NP + p) * SCH + lane];

    int   oa[9], ob[9], oc[9], od[9];
    float wa[9], wb_[9], wc[9], wd[9];
#pragma unroll
    for (int k = 0; k < 9; k++) {
        float ox = __shfl_sync(0xffffffffu, offv, 2 * k);
        float oy = __shfl_sync(0xffffffffu, offv, 2 * k + 1);
        float lx = (float)xx + (float)(k % 3 - 1) + ox;
        float ly = (float)yy + (float)(k / 3 - 1) + oy;
        lx = fminf(fmaxf(lx, 0.f), 127.f);
        ly = fminf(fmaxf(ly, 0.f), 127.f);
        float x0f = fminf(fmaxf(floorf(lx), 0.f), 127.f);
        float y0f = fminf(fmaxf(floorf(ly), 0.f), 127.f);
        float x1f = fminf(x0f + 1.f, 127.f);
        float y1f = fminf(y0f + 1.f, 127.f);
        int x0 = (int)x0f, x1 = (int)x1f, y0 = (int)y0f, y1 = (int)y1f;
        float dx1 = x1f - lx, dx0 = lx - x0f;
        float dy1 = y1f - ly, dy0 = ly - y0f;
        oa[k] = (y0 * WW + x0) * CIN;
        ob[k] = (y1 * WW + x0) * CIN;
        oc[k] = (y0 * WW + x1) * CIN;
        od[k] = (y1 * WW + x1) * CIN;
        wa[k]  = dx1 * dy1;  wb_[k] = dx1 * dy0;
        wc[k]  = dx0 * dy1;  wd[k]  = dx0 * dy0;
    }

    float va[9], vb[9], vc[9], vd[9];
#pragma unroll
    for (int k = 0; k < 9; k++) {
        va[k] = __ldg(xg + oa[k]);
        vb[k] = __ldg(xg + ob[k]);
        vc[k] = __ldg(xg + oc[k]);
        vd[k] = __ldg(xg + od[k]);
    }
#pragma unroll
    for (int k = 0; k < 9; k++)
        outp[k * 32] = __float2half_rn(
            wa[k]*va[k] + wb_[k]*vb[k] + wc[k]*vc[k] + wd[k]*vd[k]);
}

// ===========================================================================
// Kernel 2: fused depthwise(3x3) + pointwise(288->64, tf32 mma).
// Validated round-10/13 version (225us, rel_err 3.58e-4).
// ===========================================================================
#define CHUNK  96
#define SM_HALO_H (100 * CHUNK)
#define SM_HALO_F (SM_HALO_H / 2)
#define SM_Y    (64 * 100)
#define SM_PW   (96 * 72)
#define SM_DW   (9 * CHUNK)
#define SM_BASE 200
#define SM_BYTES ((SM_HALO_F + SM_Y + SM_PW + SM_DW + SM_BASE + 8) * 4)
#define OUTP    68

__global__ __launch_bounds__(512, 2) void k_dwpw(
    const float* __restrict__ dw_w,
    const float* __restrict__ dw_b,
    const float* __restrict__ pw_b,
    float* __restrict__ out)
{
    extern __shared__ float smem[];
    __half* s_hal = (__half*)smem;
    float* s_y    = smem + SM_HALO_F;
    float* s_pw   = smem + SM_HALO_F + SM_Y;
    float* s_dw   = smem + SM_HALO_F + SM_Y + SM_PW;
    const __half** s_base =
        (const __half**)(smem + SM_HALO_F + SM_Y + SM_PW + SM_DW + 8);
    float* s_red  = s_pw;
    float* s_out  = smem;

    const int tid = threadIdx.x;
    const int z   = blockIdx.z;
    const int gg  = z & 1;
    const int b   = z >> 1;
    const int ty0 = blockIdx.y * 8;
    const int tx0 = blockIdx.x * 8;

    const int warp = tid >> 5, lane = tid & 31;
    const int lg   = lane >> 2;
    const int lt   = lane & 3;
    const int team = warp >> 3;
    const int mtb  = (warp & 3) * 16;
    const int ntb  = ((warp >> 2) & 1) * 32;

    float acc[4][4];
#pragma unroll
    for (int j = 0; j < 4; j++)
#pragma unroll
        for (int q = 0; q < 4; q++) acc[j][q] = 0.f;

    float4* d4 = (float4*)s_dw;

    if (tid < 100) {
        int hy = ty0 + tid / 10 - 1, hx = tx0 + tid % 10 - 1;
        bool ok = (hy >= 0 && hy < HH && hx >= 0 && hx < WW);
        s_base[tid] = ok
            ? &g_samp16[((size_t)gg * NP + (size_t)((b * HH + hy) * WW + hx)) * SCH]
            : (const __half*)0;
    }
    __syncthreads();

    auto stage_halo = [&](int cc) {
        const int cbase = cc * CHUNK;
        if (lane < 12) {
            for (int hp = warp; hp < 100; hp += 16) {
                const __half* base = s_base[hp];
                bool ok = (base != 0);
                const void* src = ok ? (const void*)(base + cbase + lane * 8)
                                     : (const void*)g_samp16;
                cpa16(&s_hal[hp * CHUNK + lane * 8], src, ok);
            }
        }
    };

    stage_halo(0);
    CPA_COMMIT();

    for (int cc = 0; cc < 3; cc++) {
        const int cbase = cc * CHUNK;
        __syncthreads();

        for (int i = tid; i < 9 * 24; i += 512) {
            int t = i / 24, c4 = i % 24;
            cpa16(&s_dw[i * 4],
                  &dw_w[(size_t)gg * 2592 + t * SCH + cbase + c4 * 4], true);
        }
        for (int i = tid; i < 96 * 16; i += 512) {
            int c = i >> 4, f4 = i & 15;
            cpa16(&s_pw[c * 72 + f4 * 4],
                  &g_pww[((size_t)gg * SCH + cbase + c) * 64 + f4 * 4], true);
        }
        CPA_COMMIT();
        CPA_WAIT0();
        __syncthreads();

        if (tid < 384) {
            const int strip = tid / 24, c4 = tid % 24;
            const int py = strip >> 1, qx0 = (strip & 1) * 4;
            float4 bias = __ldg((const float4*)&dw_b[gg * SCH + cbase + c4 * 4]);
            float a[4][4];
#pragma unroll
            for (int oxp = 0; oxp < 4; oxp++) {
                a[oxp][0] = bias.x; a[oxp][1] = bias.y;
                a[oxp][2] = bias.z; a[oxp][3] = bias.w;
            }
#pragma unroll
            for (int ty = 0; ty < 3; ty++) {
                const __half* hrow = &s_hal[((py + ty) * 10 + qx0) * CHUNK + c4 * 4];
                float vv[6][4];
#pragma unroll
                for (int i = 0; i < 6; i++) {
                    uint2 u = *(const uint2*)&hrow[i * CHUNK];
                    float2 f01 = __half22float2(*(__half2*)&u.x);
                    float2 f23 = __half22float2(*(__half2*)&u.y);
                    vv[i][0] = f01.x; vv[i][1] = f01.y;
                    vv[i][2] = f23.x; vv[i][3] = f23.y;
                }
#pragma unroll
                for (int tx = 0; tx < 3; tx++) {
                    float4 w = d4[(ty * 3 + tx) * 24 + c4];
#pragma unroll
                    for (int oxp = 0; oxp < 4; oxp++) {
                        a[oxp][0] = fmaf(w.x, vv[oxp + tx][0], a[oxp][0]);
                        a[oxp][1] = fmaf(w.y, vv[oxp + tx][1], a[oxp][1]);
                        a[oxp][2] = fmaf(w.z, vv[oxp + tx][2], a[oxp][2]);
                        a[oxp][3] = fmaf(w.w, vv[oxp + tx][3], a[oxp][3]);
                    }
                }
            }
#pragma unroll
            for (int oxp = 0; oxp < 4; oxp++) {
                float4 r = make_float4(to_tf32(a[oxp][0]), to_tf32(a[oxp][1]),
                                       to_tf32(a[oxp][2]), to_tf32(a[oxp][3]));
                *(float4*)&s_y[(py * 8 + qx0 + oxp) * 100 + c4 * 4] = r;
            }
        }
        __syncthreads();

        if (cc < 2) {
            stage_halo(cc + 1);
            CPA_COMMIT();
        }

#pragma unroll
        for (int s = 0; s < 6; s++) {
            const int k0 = team * 48 + s * 8;
            const unsigned int* yA =
                (const unsigned int*)&s_y[(mtb + lg) * 100 + k0 + lt];
            unsigned int a0 = yA[0],   a1 = yA[800];
            unsigned int a2 = yA[4],   a3 = yA[804];
#pragma unroll
            for (int j = 0; j < 4; j++) {
                unsigned int b0 = *(const unsigned int*)
                    &s_pw[(k0 + lt    ) * 72 + ntb + j * 8 + lg];
                unsigned int b1 = *(const unsigned int*)
                    &s_pw[(k0 + lt + 4) * 72 + ntb + j * 8 + lg];
                mma_tf32(acc[j], a0, a1, a2, a3, b0, b1);
            }
        }
    }
    __syncthreads();

    if (team == 1) {
        float* dst = &s_red[((warp & 7) * 32 + lane) * 16];
#pragma unroll
        for (int j = 0; j < 4; j++)
#pragma unroll
            for (int q = 0; q < 4; q++) dst[j * 4 + q] = acc[j][q];
    }
    __syncthreads();
    if (team == 0) {
        const float* src = &s_red[((warp & 7) * 32 + lane) * 16];
        const int px0 = mtb + lg, px1 = mtb + lg + 8;
#pragma unroll
        for (int j = 0; j < 4; j++) {
            int f0 = ntb + j * 8 + 2 * lt;
            float b0v = __ldg(&pw_b[gg * GF + f0]);
            float b1v = __ldg(&pw_b[gg * GF + f0 + 1]);
            s_out[px0 * OUTP + f0]     = acc[j][0] + src[j*4+0] + b0v;
            s_out[px0 * OUTP + f0 + 1] = acc[j][1] + src[j*4+1] + b1v;
            s_out[px1 * OUTP + f0]     = acc[j][2] + src[j*4+2] + b0v;
            s_out[px1 * OUTP + f0 + 1] = acc[j][3] + src[j*4+3] + b1v;
        }
    }
    __syncthreads();

    for (int i = tid; i < 4096; i += 512) {
        int p = i >> 6, f = i & 63;
        int py = p >> 3, px = p & 7;
        out[((size_t)((b * HH + ty0 + py) * WW) + tx0 + px) * (GG * GF)
            + gg * GF + f] = s_out[p * OUTP + f];
    }
}

// ---------------------------------------------------------------------------
extern "C" void kernel_launch(void* const* d_in, const int* in_sizes, int n_in,
                              void* d_out, int out_size)
{
    const float* x     = (const float*)d_in[0];
    const float* off_w = (const float*)d_in[1];
    const float* off_b = (const float*)d_in[2];
    const float* dw_w  = (const float*)d_in[3];
    const float* dw_b  = (const float*)d_in[4];
    const float* pw_w  = (const float*)d_in[5];
    const float* pw_b  = (const float*)d_in[6];
    float* out = (float*)d_out;

    cudaFuncSetAttribute(k_offsets, cudaFuncAttributeMaxDynamicSharedMemorySize,
                         OFF_SMEM_BYTES);
    cudaFuncSetAttribute(k_dwpw, cudaFuncAttributeMaxDynamicSharedMemorySize,
                         SM_BYTES);

    k_prep<<<(GG * SCH * GF + 255) / 256, 256>>>(pw_w);
    k_offsets<<<dim3(WW/32, HH/16, BB*GG), 256, OFF_SMEM_BYTES>>>(x, off_w, off_b);
    k_sample<<<dim3(NP / 8, GG), 256>>>(x);
    k_dwpw<<<dim3(WW / 8, HH / 8, BB * GG), 512, SM_BYTES>>>(
        dw_w, dw_b, pw_b, out);
}

// round 16
// speedup vs baseline: 1.1931x; 1.0490x over previous
#include <cuda_runtime.h>
#include <cuda_fp16.h>
#include <cstdint>
#include <math.h>

// Problem constants
#define BB   8
#define HH   128
#define WW   128
#define CIN  64
#define GG   2
#define GCH  32      // channels per group
#define SCH  288     // K*K*GC
#define GF   64      // filters per group
#define NP   (BB*HH*WW)   // 131072 pixels

// Scratch
__device__ __half g_samp16[(size_t)GG * NP * SCH]; // sampled field (151 MB)
__device__ float  g_off [(size_t)GG * NP * 18];    // offsets       (19 MB)
__device__ __half g_pwwh[(size_t)GG * 144 * 64 * 2]; // pw weights fp16, k-pair interleaved

// ---------------------------------------------------------------------------
// helpers
// ---------------------------------------------------------------------------
__device__ __forceinline__ void cpa16(void* s, const void* gsrc, bool v) {
    unsigned int sa = (unsigned int)__cvta_generic_to_shared(s);
    asm volatile("cp.async.cg.shared.global [%0], [%1], 16, %2;"
                 :: "r"(sa), "l"(gsrc), "r"(v ? 16u : 0u));
}
#define CPA_COMMIT() asm volatile("cp.async.commit_group;")
#define CPA_WAIT0()  asm volatile("cp.async.wait_group 0;")

__device__ __forceinline__ void mma_f16(float* d,
    unsigned int a0, unsigned int a1, unsigned int a2, unsigned int a3,
    unsigned int b0, unsigned int b1)
{
    asm volatile(
        "mma.sync.aligned.m16n8k16.row.col.f32.f16.f16.f32 "
        "{%0,%1,%2,%3}, {%4,%5,%6,%7}, {%8,%9}, {%0,%1,%2,%3};"
        : "+f"(d[0]), "+f"(d[1]), "+f"(d[2]), "+f"(d[3])
        : "r"(a0), "r"(a1), "r"(a2), "r"(a3), "r"(b0), "r"(b1));
}

// ===========================================================================
// Kernel P: pw weights -> fp16, k-pair interleaved [g][k/2][n][2]
// ===========================================================================
__global__ void k_prep(const float* __restrict__ pw_w) {
    int i = blockIdx.x * 256 + threadIdx.x;
    if (i < GG * SCH * GF) {
        int g = i / (SCH * GF);
        int r = i % (SCH * GF);
        int c = r / GF, n = r % GF;
        g_pwwh[((size_t)(g * 144 + (c >> 1)) * 64 + n) * 2 + (c & 1)] =
            __float2half_rn(pw_w[i]);
    }
}

// ===========================================================================
// Kernel 0: offset conv (3x3, 32 -> 18) per group. (validated round-8 FFMA)
// 32x16 pixel tile, 256 threads, 2 pixels per thread. fp32 throughout --
// offset precision is safety-critical (bilinear border clip is discontinuous).
// ===========================================================================
#define OHP_W 34
#define OHP_H 18
#define XTS   17
#define XT_F  (OHP_H*OHP_W*XTS)
#define WS_F  5760
#define OFF_SMEM_BYTES ((XT_F + WS_F + 32) * 4)

__global__ __launch_bounds__(256) void k_offsets(
    const float* __restrict__ x,
    const float* __restrict__ off_w,
    const float* __restrict__ off_b)
{
    extern __shared__ float sm0[];
    float* xt   = sm0;
    float* ws   = sm0 + XT_F;
    float* wb   = sm0 + XT_F + WS_F;
    float* soff = sm0;

    const int tid = threadIdx.x;
    const int z   = blockIdx.z;
    const int g   = z & 1;
    const int b   = z >> 1;
    const int ty0 = blockIdx.y * 16;
    const int tx0 = blockIdx.x * 32;

    for (int i = tid; i < WS_F; i += 256) {
        int r = i / 20, j = i % 20;
        ws[i] = (j < 18) ? off_w[(size_t)(g * 288 + r) * 18 + j] : 0.f;
    }
    if (tid < 18) wb[tid] = off_b[g * 18 + tid];

    const int px  = tid & 31;
    const int py0 = tid >> 5;

    float acc[2][18];
#pragma unroll
    for (int pp = 0; pp < 2; pp++)
#pragma unroll
        for (int j = 0; j < 18; j++) acc[pp][j] = 0.f;

    for (int cch = 0; cch < 2; cch++) {
        __syncthreads();
        for (int i = tid; i < OHP_H * OHP_W * 16; i += 256) {
            int pos = i >> 4, c = i & 15;
            int hy = ty0 + pos / OHP_W - 1, hx = tx0 + pos % OHP_W - 1;
            float v = 0.f;
            if (hy >= 0 && hy < HH && hx >= 0 && hx < WW)
                v = x[((size_t)((b * HH + hy) * WW + hx)) * CIN
                      + g * GCH + cch * 16 + c];
            xt[pos * XTS + c] = v;
        }
        __syncthreads();

#pragma unroll 1
        for (int t = 0; t < 9; t++) {
            const int dy = t / 3, dx = t % 3;
            const float* wt = &ws[(t * 32 + cch * 16) * 20];
            const int base = (dy * OHP_W + px + dx) * XTS;
#pragma unroll 2
            for (int c = 0; c < 16; c++) {
                float v0 = xt[base + ((py0    ) * OHP_W) * XTS + c];
                float v1 = xt[base + ((py0 + 8) * OHP_W) * XTS + c];
                const float4* wv = (const float4*)&wt[c * 20];
                float4 w0 = wv[0], w1 = wv[1], w2 = wv[2], w3 = wv[3];
                float2 w4 = *(const float2*)&wt[c * 20 + 16];
#pragma unroll
                for (int pp = 0; pp < 2; pp++) {
                    float v = pp == 0 ? v0 : v1;
                    acc[pp][ 0] = fmaf(v, w0.x, acc[pp][ 0]);
                    acc[pp][ 1] = fmaf(v, w0.y, acc[pp][ 1]);
                    acc[pp][ 2] = fmaf(v, w0.z, acc[pp][ 2]);
                    acc[pp][ 3] = fmaf(v, w0.w, acc[pp][ 3]);
                    acc[pp][ 4] = fmaf(v, w1.x, acc[pp][ 4]);
                    acc[pp][ 5] = fmaf(v, w1.y, acc[pp][ 5]);
                    acc[pp][ 6] = fmaf(v, w1.z, acc[pp][ 6]);
                    acc[pp][ 7] = fmaf(v, w1.w, acc[pp][ 7]);
                    acc[pp][ 8] = fmaf(v, w2.x, acc[pp][ 8]);
                    acc[pp][ 9] = fmaf(v, w2.y, acc[pp][ 9]);
                    acc[pp][10] = fmaf(v, w2.z, acc[pp][10]);
                    acc[pp][11] = fmaf(v, w2.w, acc[pp][11]);
                    acc[pp][12] = fmaf(v, w3.x, acc[pp][12]);
                    acc[pp][13] = fmaf(v, w3.y, acc[pp][13]);
                    acc[pp][14] = fmaf(v, w3.z, acc[pp][14]);
                    acc[pp][15] = fmaf(v, w3.w, acc[pp][15]);
                    acc[pp][16] = fmaf(v, w4.x, acc[pp][16]);
                    acc[pp][17] = fmaf(v, w4.y, acc[pp][17]);
                }
            }
        }
    }
    __syncthreads();

#pragma unroll
    for (int pp = 0; pp < 2; pp++) {
        const int p = (py0 + pp * 8) * 32 + px;
#pragma unroll
        for (int j = 0; j < 18; j++)
            soff[p * 18 + j] = acc[pp][j] + wb[j];
    }
    __syncthreads();

    const size_t pbase = (size_t)b * (HH * WW) + (size_t)ty0 * WW + tx0;
    for (int i = tid; i < 32 * 16 * 18; i += 256) {
        int row = i / 576, rem = i % 576;
        g_off[((size_t)g * NP + pbase + (size_t)row * WW) * 18 + rem] = soff[i];
    }
}

// ===========================================================================
// Kernel 1: bilinear sampling (validated round-10; MLP-12 tap batching).
// fp16 output. fp32 per-tap arithmetic identical to reference.
// ===========================================================================
__global__ __launch_bounds__(256) void k_sample(
    const float* __restrict__ x)
{
    const int tid  = threadIdx.x;
    const int g    = blockIdx.y;
    const int warp = tid >> 5, lane = tid & 31;
    const int p   = blockIdx.x * 8 + warp;
    const int b   = p >> 14;
    const int rem = p & 16383;
    const int yy  = rem >> 7;
    const int xx  = rem & 127;

    float offv = 0.f;
    if (lane < 18) offv = g_off[((size_t)g * NP + p) * 18 + lane];

    const float* xg = x + (size_t)b * (HH * WW) * CIN + g * GCH + lane;
    __half* outp = &g_samp16[((size_t)g * NP + p) * SCH + lane];

#pragma unroll
    for (int grp = 0; grp < 3; grp++) {
        float wa[3], wb_[3], wc[3], wd[3];
        int oa[3], ob[3], oc[3], od[3];
#pragma unroll
        for (int j = 0; j < 3; j++) {
            const int k = grp * 3 + j;
            float ox = __shfl_sync(0xffffffffu, offv, 2 * k);
            float oy = __shfl_sync(0xffffffffu, offv, 2 * k + 1);
            float lx = (float)xx + (float)(k % 3 - 1) + ox;
            float ly = (float)yy + (float)(k / 3 - 1) + oy;
            lx = fminf(fmaxf(lx, 0.f), 127.f);
            ly = fminf(fmaxf(ly, 0.f), 127.f);
            float x0f = fminf(fmaxf(floorf(lx), 0.f), 127.f);
            float y0f = fminf(fmaxf(floorf(ly), 0.f), 127.f);
            float x1f = fminf(x0f + 1.f, 127.f);
            float y1f = fminf(y0f + 1.f, 127.f);
            int x0 = (int)x0f, x1 = (int)x1f, y0 = (int)y0f, y1 = (int)y1f;
            float dx1 = x1f - lx, dx0 = lx - x0f;
            float dy1 = y1f - ly, dy0 = ly - y0f;
            oa[j] = (y0 * WW + x0) * CIN;
            ob[j] = (y1 * WW + x0) * CIN;
            oc[j] = (y0 * WW + x1) * CIN;
            od[j] = (y1 * WW + x1) * CIN;
            wa[j]  = dx1 * dy1;  wb_[j] = dx1 * dy0;
            wc[j]  = dx0 * dy1;  wd[j]  = dx0 * dy0;
        }
        float va[3], vb[3], vc[3], vd[3];
#pragma unroll
        for (int j = 0; j < 3; j++) {
            va[j] = __ldg(xg + oa[j]);
            vb[j] = __ldg(xg + ob[j]);
            vc[j] = __ldg(xg + oc[j]);
            vd[j] = __ldg(xg + od[j]);
        }
#pragma unroll
        for (int j = 0; j < 3; j++)
            outp[(grp * 3 + j) * 32] = __float2half_rn(
                wa[j]*va[j] + wb_[j]*vb[j] + wc[j]*vc[j] + wd[j]*vd[j]);
    }
}

// ===========================================================================
// Kernel 2: fused depthwise(3x3) + pointwise(288->64, fp16 mma, fp32 accum).
// 8x8 tile per (b,g), 512 threads, 3 channel chunks of 96.
// y fp16 smem [64][104] (conflict-free, stride 52 half2); pw fp16 k-pair
// interleaved [48 kp][144] (stride 72 half2). Layout validated in round 11.
// ===========================================================================
#define CHUNK  96
#define SM_HALO_F 4800            // halo: 9600 halves
#define YH_F     3328             // y: 64 x 104 halves (float-equiv)
#define PWH_F    3456             // pw: 48 x 144 halves (float-equiv)
#define DW_F     864
#define OFS_YH   SM_HALO_F
#define OFS_PWH  (SM_HALO_F + YH_F)
#define OFS_DW   (SM_HALO_F + YH_F + PWH_F)
#define OFS_BASE (OFS_DW + DW_F)
#define SM_BYTES ((OFS_BASE + 200 + 8) * 4)
#define OUTP    68

__global__ __launch_bounds__(512, 2) void k_dwpw(
    const float* __restrict__ dw_w,   // [G,3,3,288,1]
    const float* __restrict__ dw_b,   // [G,288]
    const float* __restrict__ pw_b,   // [G,64]
    float* __restrict__ out)          // [B,H,W,128]
{
    extern __shared__ float smem[];
    __half* s_hal  = (__half*)smem;
    __half* s_yh   = (__half*)(smem + OFS_YH);
    __half* s_pwh  = (__half*)(smem + OFS_PWH);
    float*  s_dw   = smem + OFS_DW;
    const __half** s_base = (const __half**)(smem + OFS_BASE);
    float* s_red = smem;                // post-loop aliases (halo dead)
    float* s_out = smem + OFS_YH;       // overlays yh/pwh/dw (dead)

    const int tid = threadIdx.x;
    const int z   = blockIdx.z;
    const int gg  = z & 1;
    const int b   = z >> 1;
    const int ty0 = blockIdx.y * 8;
    const int tx0 = blockIdx.x * 8;

    const int warp = tid >> 5, lane = tid & 31;
    const int lg   = lane >> 2;
    const int lt   = lane & 3;
    const int team = warp >> 3;
    const int mtb  = (warp & 3) * 16;
    const int ntb  = ((warp >> 2) & 1) * 32;

    float acc[4][4];
#pragma unroll
    for (int j = 0; j < 4; j++)
#pragma unroll
        for (int q = 0; q < 4; q++) acc[j][q] = 0.f;

    float4* d4 = (float4*)s_dw;

    if (tid < 100) {
        int hy = ty0 + tid / 10 - 1, hx = tx0 + tid % 10 - 1;
        bool ok = (hy >= 0 && hy < HH && hx >= 0 && hx < WW);
        s_base[tid] = ok
            ? &g_samp16[((size_t)gg * NP + (size_t)((b * HH + hy) * WW + hx)) * SCH]
            : (const __half*)0;
    }
    __syncthreads();

    auto stage_halo = [&](int cc) {
        const int cbase = cc * CHUNK;
        if (lane < 12) {
            for (int hp = warp; hp < 100; hp += 16) {
                const __half* base = s_base[hp];
                bool ok = (base != 0);
                const void* src = ok ? (const void*)(base + cbase + lane * 8)
                                     : (const void*)g_samp16;
                cpa16(&s_hal[hp * CHUNK + lane * 8], src, ok);
            }
        }
    };

    stage_halo(0);
    CPA_COMMIT();

    for (int cc = 0; cc < 3; cc++) {
        const int cbase = cc * CHUNK;
        __syncthreads();

        // stage dw weights + fp16 pw weight chunk (async)
        for (int i = tid; i < 9 * 24; i += 512) {
            int t = i / 24, c4 = i % 24;
            cpa16(&s_dw[i * 4],
                  &dw_w[(size_t)gg * 2592 + t * SCH + cbase + c4 * 4], true);
        }
        for (int i = tid; i < 48 * 16; i += 512) {
            int kp = i >> 4, seg = i & 15;
            cpa16(&s_pwh[kp * 144 + seg * 8],
                  &g_pwwh[((size_t)(gg * 144 + cc * 48 + kp)) * 128 + seg * 8],
                  true);
        }
        CPA_COMMIT();
        CPA_WAIT0();
        __syncthreads();

        // --- depthwise 3x3: strip 4 px x 4 ch per thread; fp32 accum,
        //     fp16 store (round-to-nearest) ---
        if (tid < 384) {
            const int strip = tid / 24, c4 = tid % 24;
            const int py = strip >> 1, qx0 = (strip & 1) * 4;
            float4 bias = __ldg((const float4*)&dw_b[gg * SCH + cbase + c4 * 4]);
            float a[4][4];
#pragma unroll
            for (int oxp = 0; oxp < 4; oxp++) {
                a[oxp][0] = bias.x; a[oxp][1] = bias.y;
                a[oxp][2] = bias.z; a[oxp][3] = bias.w;
            }
#pragma unroll
            for (int ty = 0; ty < 3; ty++) {
                const __half* hrow = &s_hal[((py + ty) * 10 + qx0) * CHUNK + c4 * 4];
                float vv[6][4];
#pragma unroll
                for (int i = 0; i < 6; i++) {
                    uint2 u = *(const uint2*)&hrow[i * CHUNK];
                    float2 f01 = __half22float2(*(__half2*)&u.x);
                    float2 f23 = __half22float2(*(__half2*)&u.y);
                    vv[i][0] = f01.x; vv[i][1] = f01.y;
                    vv[i][2] = f23.x; vv[i][3] = f23.y;
                }
#pragma unroll
                for (int tx = 0; tx < 3; tx++) {
                    float4 w = d4[(ty * 3 + tx) * 24 + c4];
#pragma unroll
                    for (int oxp = 0; oxp < 4; oxp++) {
                        a[oxp][0] = fmaf(w.x, vv[oxp + tx][0], a[oxp][0]);
                        a[oxp][1] = fmaf(w.y, vv[oxp + tx][1], a[oxp][1]);
                        a[oxp][2] = fmaf(w.z, vv[oxp + tx][2], a[oxp][2]);
                        a[oxp][3] = fmaf(w.w, vv[oxp + tx][3], a[oxp][3]);
                    }
                }
            }
#pragma unroll
            for (int oxp = 0; oxp < 4; oxp++) {
                __half2 h01 = __floats2half2_rn(a[oxp][0], a[oxp][1]);
                __half2 h23 = __floats2half2_rn(a[oxp][2], a[oxp][3]);
                uint2 u;
                u.x = *(unsigned int*)&h01;
                u.y = *(unsigned int*)&h23;
                *(uint2*)&s_yh[(py * 8 + qx0 + oxp) * 104 + c4 * 4] = u;
            }
        }
        __syncthreads();   // y ready; halo dead

        if (cc < 2) {
            stage_halo(cc + 1);
            CPA_COMMIT();
        }

        // --- pointwise via fp16 mma (m16n8k16): team's 48-channel K slice ---
        const unsigned int* yrow = (const unsigned int*)s_yh;   // half2, stride 52
        const unsigned int* pw2  = (const unsigned int*)s_pwh;  // half2, stride 72
#pragma unroll
        for (int s = 0; s < 3; s++) {
            const int kh0 = team * 24 + s * 8;   // half2 (=k-pair) offset
            unsigned int a0 = yrow[(mtb + lg    ) * 52 + kh0 + lt];
            unsigned int a1 = yrow[(mtb + lg + 8) * 52 + kh0 + lt];
            unsigned int a2 = yrow[(mtb + lg    ) * 52 + kh0 + lt + 4];
            unsigned int a3 = yrow[(mtb + lg + 8) * 52 + kh0 + lt + 4];
#pragma unroll
            for (int j = 0; j < 4; j++) {
                unsigned int b0 = pw2[(kh0 + lt    ) * 72 + ntb + j * 8 + lg];
                unsigned int b1 = pw2[(kh0 + lt + 4) * 72 + ntb + j * 8 + lg];
                mma_f16(acc[j], a0, a1, a2, a3, b0, b1);
            }
        }
    }
    __syncthreads();

    // split-K reduce across teams
    if (team == 1) {
        float* dst = &s_red[((warp & 7) * 32 + lane) * 16];
#pragma unroll
        for (int j = 0; j < 4; j++)
#pragma unroll
            for (int q = 0; q < 4; q++) dst[j * 4 + q] = acc[j][q];
    }
    __syncthreads();
    if (team == 0) {
        const float* src = &s_red[((warp & 7) * 32 + lane) * 16];
        const int px0 = mtb + lg, px1 = mtb + lg + 8;
#pragma unroll
        for (int j = 0; j < 4; j++) {
            int f0 = ntb + j * 8 + 2 * lt;
            float b0v = __ldg(&pw_b[gg * GF + f0]);
            float b1v = __ldg(&pw_b[gg * GF + f0 + 1]);
            s_out[px0 * OUTP + f0]     = acc[j][0] + src[j*4+0] + b0v;
            s_out[px0 * OUTP + f0 + 1] = acc[j][1] + src[j*4+1] + b1v;
            s_out[px1 * OUTP + f0]     = acc[j][2] + src[j*4+2] + b0v;
            s_out[px1 * OUTP + f0 + 1] = acc[j][3] + src[j*4+3] + b1v;
        }
    }
    __syncthreads();

    for (int i = tid; i < 4096; i += 512) {
        int p = i >> 6, f = i & 63;
        int py = p >> 3, px = p & 7;
        out[((size_t)((b * HH + ty0 + py) * WW) + tx0 + px) * (GG * GF)
            + gg * GF + f] = s_out[p * OUTP + f];
    }
}

// ---------------------------------------------------------------------------
extern "C" void kernel_launch(void* const* d_in, const int* in_sizes, int n_in,
                              void* d_out, int out_size)
{
    const float* x     = (const float*)d_in[0];
    const float* off_w = (const float*)d_in[1];
    const float* off_b = (const float*)d_in[2];
    const float* dw_w  = (const float*)d_in[3];
    const float* dw_b  = (const float*)d_in[4];
    const float* pw_w  = (const float*)d_in[5];
    const float* pw_b  = (const float*)d_in[6];
    float* out = (float*)d_out;

    cudaFuncSetAttribute(k_offsets, cudaFuncAttributeMaxDynamicSharedMemorySize,
                         OFF_SMEM_BYTES);
    cudaFuncSetAttribute(k_dwpw, cudaFuncAttributeMaxDynamicSharedMemorySize,
                         SM_BYTES);

    k_prep<<<(GG * SCH * GF + 255) / 256, 256>>>(pw_w);
    k_offsets<<<dim3(WW/32, HH/16, BB*GG), 256, OFF_SMEM_BYTES>>>(x, off_w, off_b);
    k_sample<<<dim3(NP / 8, GG), 256>>>(x);
    k_dwpw<<<dim3(WW / 8, HH / 8, BB * GG), 512, SM_BYTES>>>(
        dw_w, dw_b, pw_b, out);
}

// round 17
// speedup vs baseline: 1.3373x; 1.1208x over previous
#include <cuda_runtime.h>
#include <cuda_fp16.h>
#include <cstdint>
#include <math.h>

// Problem constants
#define BB   8
#define HH   128
#define WW   128
#define CIN  64
#define GG   2
#define GCH  32      // channels per group
#define SCH  288     // K*K*GC
#define GF   64      // filters per group
#define NP   (BB*HH*WW)   // 131072 pixels

// Scratch
__device__ __half g_samp16[(size_t)GG * NP * SCH]; // sampled field (151 MB)
__device__ float  g_off [(size_t)GG * NP * 18];    // offsets       (19 MB)
__device__ __half g_pwwh[(size_t)GG * 144 * 64 * 2]; // pw weights fp16, k-pair interleaved

// ---------------------------------------------------------------------------
// helpers
// ---------------------------------------------------------------------------
__device__ __forceinline__ void cpa16(void* s, const void* gsrc, bool v) {
    unsigned int sa = (unsigned int)__cvta_generic_to_shared(s);
    asm volatile("cp.async.cg.shared.global [%0], [%1], 16, %2;"
                 :: "r"(sa), "l"(gsrc), "r"(v ? 16u : 0u));
}
#define CPA_COMMIT() asm volatile("cp.async.commit_group;")
#define CPA_WAIT0()  asm volatile("cp.async.wait_group 0;")

__device__ __forceinline__ void mma_f16(float* d,
    unsigned int a0, unsigned int a1, unsigned int a2, unsigned int a3,
    unsigned int b0, unsigned int b1)
{
    asm volatile(
        "mma.sync.aligned.m16n8k16.row.col.f32.f16.f16.f32 "
        "{%0,%1,%2,%3}, {%4,%5,%6,%7}, {%8,%9}, {%0,%1,%2,%3};"
        : "+f"(d[0]), "+f"(d[1]), "+f"(d[2]), "+f"(d[3])
        : "r"(a0), "r"(a1), "r"(a2), "r"(a3), "r"(b0), "r"(b1));
}

// ===========================================================================
// Kernel P: pw weights -> fp16, k-pair interleaved [g][k/2][n][2]
// ===========================================================================
__global__ void k_prep(const float* __restrict__ pw_w) {
    int i = blockIdx.x * 256 + threadIdx.x;
    if (i < GG * SCH * GF) {
        int g = i / (SCH * GF);
        int r = i % (SCH * GF);
        int c = r / GF, n = r % GF;
        g_pwwh[((size_t)(g * 144 + (c >> 1)) * 64 + n) * 2 + (c & 1)] =
            __float2half_rn(pw_w[i]);
    }
}

// ===========================================================================
// Kernel 0: offset conv (3x3, 32 -> 18) per group. (validated round-8 FFMA)
// fp32 throughout -- offset precision is safety-critical (border clip is
// discontinuous in the offset).
// ===========================================================================
#define OHP_W 34
#define OHP_H 18
#define XTS   17
#define XT_F  (OHP_H*OHP_W*XTS)
#define WS_F  5760
#define OFF_SMEM_BYTES ((XT_F + WS_F + 32) * 4)

__global__ __launch_bounds__(256) void k_offsets(
    const float* __restrict__ x,
    const float* __restrict__ off_w,
    const float* __restrict__ off_b)
{
    extern __shared__ float sm0[];
    float* xt   = sm0;
    float* ws   = sm0 + XT_F;
    float* wb   = sm0 + XT_F + WS_F;
    float* soff = sm0;

    const int tid = threadIdx.x;
    const int z   = blockIdx.z;
    const int g   = z & 1;
    const int b   = z >> 1;
    const int ty0 = blockIdx.y * 16;
    const int tx0 = blockIdx.x * 32;

    for (int i = tid; i < WS_F; i += 256) {
        int r = i / 20, j = i % 20;
        ws[i] = (j < 18) ? off_w[(size_t)(g * 288 + r) * 18 + j] : 0.f;
    }
    if (tid < 18) wb[tid] = off_b[g * 18 + tid];

    const int px  = tid & 31;
    const int py0 = tid >> 5;

    float acc[2][18];
#pragma unroll
    for (int pp = 0; pp < 2; pp++)
#pragma unroll
        for (int j = 0; j < 18; j++) acc[pp][j] = 0.f;

    for (int cch = 0; cch < 2; cch++) {
        __syncthreads();
        for (int i = tid; i < OHP_H * OHP_W * 16; i += 256) {
            int pos = i >> 4, c = i & 15;
            int hy = ty0 + pos / OHP_W - 1, hx = tx0 + pos % OHP_W - 1;
            float v = 0.f;
            if (hy >= 0 && hy < HH && hx >= 0 && hx < WW)
                v = x[((size_t)((b * HH + hy) * WW + hx)) * CIN
                      + g * GCH + cch * 16 + c];
            xt[pos * XTS + c] = v;
        }
        __syncthreads();

#pragma unroll 1
        for (int t = 0; t < 9; t++) {
            const int dy = t / 3, dx = t % 3;
            const float* wt = &ws[(t * 32 + cch * 16) * 20];
            const int base = (dy * OHP_W + px + dx) * XTS;
#pragma unroll 2
            for (int c = 0; c < 16; c++) {
                float v0 = xt[base + ((py0    ) * OHP_W) * XTS + c];
                float v1 = xt[base + ((py0 + 8) * OHP_W) * XTS + c];
                const float4* wv = (const float4*)&wt[c * 20];
                float4 w0 = wv[0], w1 = wv[1], w2 = wv[2], w3 = wv[3];
                float2 w4 = *(const float2*)&wt[c * 20 + 16];
#pragma unroll
                for (int pp = 0; pp < 2; pp++) {
                    float v = pp == 0 ? v0 : v1;
                    acc[pp][ 0] = fmaf(v, w0.x, acc[pp][ 0]);
                    acc[pp][ 1] = fmaf(v, w0.y, acc[pp][ 1]);
                    acc[pp][ 2] = fmaf(v, w0.z, acc[pp][ 2]);
                    acc[pp][ 3] = fmaf(v, w0.w, acc[pp][ 3]);
                    acc[pp][ 4] = fmaf(v, w1.x, acc[pp][ 4]);
                    acc[pp][ 5] = fmaf(v, w1.y, acc[pp][ 5]);
                    acc[pp][ 6] = fmaf(v, w1.z, acc[pp][ 6]);
                    acc[pp][ 7] = fmaf(v, w1.w, acc[pp][ 7]);
                    acc[pp][ 8] = fmaf(v, w2.x, acc[pp][ 8]);
                    acc[pp][ 9] = fmaf(v, w2.y, acc[pp][ 9]);
                    acc[pp][10] = fmaf(v, w2.z, acc[pp][10]);
                    acc[pp][11] = fmaf(v, w2.w, acc[pp][11]);
                    acc[pp][12] = fmaf(v, w3.x, acc[pp][12]);
                    acc[pp][13] = fmaf(v, w3.y, acc[pp][13]);
                    acc[pp][14] = fmaf(v, w3.z, acc[pp][14]);
                    acc[pp][15] = fmaf(v, w3.w, acc[pp][15]);
                    acc[pp][16] = fmaf(v, w4.x, acc[pp][16]);
                    acc[pp][17] = fmaf(v, w4.y, acc[pp][17]);
                }
            }
        }
    }
    __syncthreads();

#pragma unroll
    for (int pp = 0; pp < 2; pp++) {
        const int p = (py0 + pp * 8) * 32 + px;
#pragma unroll
        for (int j = 0; j < 18; j++)
            soff[p * 18 + j] = acc[pp][j] + wb[j];
    }
    __syncthreads();

    const size_t pbase = (size_t)b * (HH * WW) + (size_t)ty0 * WW + tx0;
    for (int i = tid; i < 32 * 16 * 18; i += 256) {
        int row = i / 576, rem = i % 576;
        g_off[((size_t)g * NP + pbase + (size_t)row * WW) * 18 + rem] = soff[i];
    }
}

// ===========================================================================
// Kernel 1: bilinear sampling (validated round-10; MLP-12 tap batching).
// fp16 output. fp32 per-tap arithmetic identical to reference.
// ===========================================================================
__global__ __launch_bounds__(256) void k_sample(
    const float* __restrict__ x)
{
    const int tid  = threadIdx.x;
    const int g    = blockIdx.y;
    const int warp = tid >> 5, lane = tid & 31;
    const int p   = blockIdx.x * 8 + warp;
    const int b   = p >> 14;
    const int rem = p & 16383;
    const int yy  = rem >> 7;
    const int xx  = rem & 127;

    float offv = 0.f;
    if (lane < 18) offv = g_off[((size_t)g * NP + p) * 18 + lane];

    const float* xg = x + (size_t)b * (HH * WW) * CIN + g * GCH + lane;
    __half* outp = &g_samp16[((size_t)g * NP + p) * SCH + lane];

#pragma unroll
    for (int grp = 0; grp < 3; grp++) {
        float wa[3], wb_[3], wc[3], wd[3];
        int oa[3], ob[3], oc[3], od[3];
#pragma unroll
        for (int j = 0; j < 3; j++) {
            const int k = grp * 3 + j;
            float ox = __shfl_sync(0xffffffffu, offv, 2 * k);
            float oy = __shfl_sync(0xffffffffu, offv, 2 * k + 1);
            float lx = (float)xx + (float)(k % 3 - 1) + ox;
            float ly = (float)yy + (float)(k / 3 - 1) + oy;
            lx = fminf(fmaxf(lx, 0.f), 127.f);
            ly = fminf(fmaxf(ly, 0.f), 127.f);
            float x0f = fminf(fmaxf(floorf(lx), 0.f), 127.f);
            float y0f = fminf(fmaxf(floorf(ly), 0.f), 127.f);
            float x1f = fminf(x0f + 1.f, 127.f);
            float y1f = fminf(y0f + 1.f, 127.f);
            int x0 = (int)x0f, x1 = (int)x1f, y0 = (int)y0f, y1 = (int)y1f;
            float dx1 = x1f - lx, dx0 = lx - x0f;
            float dy1 = y1f - ly, dy0 = ly - y0f;
            oa[j] = (y0 * WW + x0) * CIN;
            ob[j] = (y1 * WW + x0) * CIN;
            oc[j] = (y0 * WW + x1) * CIN;
            od[j] = (y1 * WW + x1) * CIN;
            wa[j]  = dx1 * dy1;  wb_[j] = dx1 * dy0;
            wc[j]  = dx0 * dy1;  wd[j]  = dx0 * dy0;
        }
        float va[3], vb[3], vc[3], vd[3];
#pragma unroll
        for (int j = 0; j < 3; j++) {
            va[j] = __ldg(xg + oa[j]);
            vb[j] = __ldg(xg + ob[j]);
            vc[j] = __ldg(xg + oc[j]);
            vd[j] = __ldg(xg + od[j]);
        }
#pragma unroll
        for (int j = 0; j < 3; j++)
            outp[(grp * 3 + j) * 32] = __float2half_rn(
                wa[j]*va[j] + wb_[j]*vb[j] + wc[j]*vc[j] + wd[j]*vd[j]);
    }
}

// ===========================================================================
// Kernel 2: fused depthwise(3x3) + pointwise(288->64, fp16 mma, fp32 accum).
// 16x8 pixel tile per (b,g) [128 px/block], 512 threads, 3 chunks of 96 ch.
// NO split-K: 16 warps = 8 m-tiles(16 px) x 2 n-halves(32 f), full K per warp.
// Halves per-pixel weight staging, halo redundancy 1.56->1.40, drops the
// split-K reduce round trip. Fragment layouts identical to validated r16.
// ===========================================================================
#define CHUNK  96
#define HPW    18                    // halo width
#define HPH    10                    // halo height
#define NHALO  180
#define SM_HALO_F (NHALO * CHUNK / 2)   // 8640 fl (17280 halves)
#define YH_F     (128 * 104 / 2)        // 6656 fl
#define PWH_F    3456                   // 48 kp x 144 halves
#define DW_F     864
#define OFS_YH   SM_HALO_F
#define OFS_PWH  (SM_HALO_F + YH_F)
#define OFS_DW   (SM_HALO_F + YH_F + PWH_F)
#define OFS_BASE (OFS_DW + DW_F)
#define SM_BYTES ((OFS_BASE + 2 * NHALO + 8) * 4)
#define OUTP    68

__global__ __launch_bounds__(512, 2) void k_dwpw(
    const float* __restrict__ dw_w,   // [G,3,3,288,1]
    const float* __restrict__ dw_b,   // [G,288]
    const float* __restrict__ pw_b,   // [G,64]
    float* __restrict__ out)          // [B,H,W,128]
{
    extern __shared__ float smem[];
    __half* s_hal  = (__half*)smem;
    __half* s_yh   = (__half*)(smem + OFS_YH);
    __half* s_pwh  = (__half*)(smem + OFS_PWH);
    float*  s_dw   = smem + OFS_DW;
    const __half** s_base = (const __half**)(smem + OFS_BASE);
    float* s_out = smem;                // alias: 128*68 = 8704 fl (all dead)

    const int tid = threadIdx.x;
    const int z   = blockIdx.z;
    const int gg  = z & 1;
    const int b   = z >> 1;
    const int ty0 = blockIdx.y * 8;
    const int tx0 = blockIdx.x * 16;

    const int warp = tid >> 5, lane = tid & 31;
    const int lg   = lane >> 2;
    const int lt   = lane & 3;
    const int mtb  = (warp >> 1) * 16;    // m-tile base (px 0..112)
    const int ntb  = (warp & 1) * 32;     // n-half base

    float acc[4][4];
#pragma unroll
    for (int j = 0; j < 4; j++)
#pragma unroll
        for (int q = 0; q < 4; q++) acc[j][q] = 0.f;

    float4* d4 = (float4*)s_dw;

    if (tid < NHALO) {
        int hy = ty0 + tid / HPW - 1, hx = tx0 + tid % HPW - 1;
        bool ok = (hy >= 0 && hy < HH && hx >= 0 && hx < WW);
        s_base[tid] = ok
            ? &g_samp16[((size_t)gg * NP + (size_t)((b * HH + hy) * WW + hx)) * SCH]
            : (const __half*)0;
    }
    __syncthreads();

    auto stage_halo = [&](int cc) {
        const int cbase = cc * CHUNK;
        if (lane < 12) {
            for (int hp = warp; hp < NHALO; hp += 16) {
                const __half* base = s_base[hp];
                bool ok = (base != 0);
                const void* src = ok ? (const void*)(base + cbase + lane * 8)
                                     : (const void*)g_samp16;
                cpa16(&s_hal[hp * CHUNK + lane * 8], src, ok);
            }
        }
    };

    stage_halo(0);
    CPA_COMMIT();

    for (int cc = 0; cc < 3; cc++) {
        const int cbase = cc * CHUNK;
        __syncthreads();

        // stage dw weights + fp16 pw weight chunk (async)
        for (int i = tid; i < 9 * 24; i += 512) {
            int t = i / 24, c4 = i % 24;
            cpa16(&s_dw[i * 4],
                  &dw_w[(size_t)gg * 2592 + t * SCH + cbase + c4 * 4], true);
        }
        for (int i = tid; i < 48 * 16; i += 512) {
            int kp = i >> 4, seg = i & 15;
            cpa16(&s_pwh[kp * 144 + seg * 8],
                  &g_pwwh[((size_t)(gg * 144 + cc * 48 + kp)) * 128 + seg * 8],
                  true);
        }
        CPA_COMMIT();
        CPA_WAIT0();
        __syncthreads();

        // --- depthwise 3x3: strip 4 px x 4 ch; 768 items over 512 threads ---
        for (int i = tid; i < 768; i += 512) {
            const int c4 = i % 24;
            const int strip = i / 24;            // 0..31
            const int py = strip >> 2, qx0 = (strip & 3) * 4;
            float4 bias = __ldg((const float4*)&dw_b[gg * SCH + cbase + c4 * 4]);
            float a[4][4];
#pragma unroll
            for (int oxp = 0; oxp < 4; oxp++) {
                a[oxp][0] = bias.x; a[oxp][1] = bias.y;
                a[oxp][2] = bias.z; a[oxp][3] = bias.w;
            }
#pragma unroll
            for (int ty = 0; ty < 3; ty++) {
                const __half* hrow = &s_hal[((py + ty) * HPW + qx0) * CHUNK + c4 * 4];
                float vv[6][4];
#pragma unroll
                for (int q = 0; q < 6; q++) {
                    uint2 u = *(const uint2*)&hrow[q * CHUNK];
                    float2 f01 = __half22float2(*(__half2*)&u.x);
                    float2 f23 = __half22float2(*(__half2*)&u.y);
                    vv[q][0] = f01.x; vv[q][1] = f01.y;
                    vv[q][2] = f23.x; vv[q][3] = f23.y;
                }
#pragma unroll
                for (int tx = 0; tx < 3; tx++) {
                    float4 w = d4[(ty * 3 + tx) * 24 + c4];
#pragma unroll
                    for (int oxp = 0; oxp < 4; oxp++) {
                        a[oxp][0] = fmaf(w.x, vv[oxp + tx][0], a[oxp][0]);
                        a[oxp][1] = fmaf(w.y, vv[oxp + tx][1], a[oxp][1]);
                        a[oxp][2] = fmaf(w.z, vv[oxp + tx][2], a[oxp][2]);
                        a[oxp][3] = fmaf(w.w, vv[oxp + tx][3], a[oxp][3]);
                    }
                }
            }
#pragma unroll
            for (int oxp = 0; oxp < 4; oxp++) {
                __half2 h01 = __floats2half2_rn(a[oxp][0], a[oxp][1]);
                __half2 h23 = __floats2half2_rn(a[oxp][2], a[oxp][3]);
                uint2 u;
                u.x = *(unsigned int*)&h01;
                u.y = *(unsigned int*)&h23;
                *(uint2*)&s_yh[(py * 16 + qx0 + oxp) * 104 + c4 * 4] = u;
            }
        }
        __syncthreads();   // y ready; halo dead

        if (cc < 2) {
            stage_halo(cc + 1);
            CPA_COMMIT();
        }

        // --- pointwise via fp16 mma: full 48 k-pairs per warp ---
        const unsigned int* yrow = (const unsigned int*)s_yh;   // half2, stride 52
        const unsigned int* pw2  = (const unsigned int*)s_pwh;  // half2, stride 72
#pragma unroll
        for (int s = 0; s < 6; s++) {
            const int kh0 = s * 8;
            unsigned int a0 = yrow[(mtb + lg    ) * 52 + kh0 + lt];
            unsigned int a1 = yrow[(mtb + lg + 8) * 52 + kh0 + lt];
            unsigned int a2 = yrow[(mtb + lg    ) * 52 + kh0 + lt + 4];
            unsigned int a3 = yrow[(mtb + lg + 8) * 52 + kh0 + lt + 4];
#pragma unroll
            for (int j = 0; j < 4; j++) {
                unsigned int b0 = pw2[(kh0 + lt    ) * 72 + ntb + j * 8 + lg];
                unsigned int b1 = pw2[(kh0 + lt + 4) * 72 + ntb + j * 8 + lg];
                mma_f16(acc[j], a0, a1, a2, a3, b0, b1);
            }
        }
    }
    __syncthreads();   // all smem consumers done -> safe to overlay s_out

    // epilogue: bias + stage to s_out (no split-K reduce needed)
    {
        const int px0 = mtb + lg, px1 = mtb + lg + 8;
#pragma unroll
        for (int j = 0; j < 4; j++) {
            int f0 = ntb + j * 8 + 2 * lt;
            float b0v = __ldg(&pw_b[gg * GF + f0]);
            float b1v = __ldg(&pw_b[gg * GF + f0 + 1]);
            s_out[px0 * OUTP + f0]     = acc[j][0] + b0v;
            s_out[px0 * OUTP + f0 + 1] = acc[j][1] + b1v;
            s_out[px1 * OUTP + f0]     = acc[j][2] + b0v;
            s_out[px1 * OUTP + f0 + 1] = acc[j][3] + b1v;
        }
    }
    __syncthreads();

    // coalesced store: 128 px x 64 f
    for (int i = tid; i < 8192; i += 512) {
        int p = i >> 6, f = i & 63;
        int py = p >> 4, px = p & 15;
        out[((size_t)((b * HH + ty0 + py) * WW) + tx0 + px) * (GG * GF)
            + gg * GF + f] = s_out[p * OUTP + f];
    }
}

// ---------------------------------------------------------------------------
extern "C" void kernel_launch(void* const* d_in, const int* in_sizes, int n_in,
                              void* d_out, int out_size)
{
    const float* x     = (const float*)d_in[0];
    const float* off_w = (const float*)d_in[1];
    const float* off_b = (const float*)d_in[2];
    const float* dw_w  = (const float*)d_in[3];
    const float* dw_b  = (const float*)d_in[4];
    const float* pw_w  = (const float*)d_in[5];
    const float* pw_b  = (const float*)d_in[6];
    float* out = (float*)d_out;

    cudaFuncSetAttribute(k_offsets, cudaFuncAttributeMaxDynamicSharedMemorySize,
                         OFF_SMEM_BYTES);
    cudaFuncSetAttribute(k_dwpw, cudaFuncAttributeMaxDynamicSharedMemorySize,
                         SM_BYTES);

    k_prep<<<(GG * SCH * GF + 255) / 256, 256>>>(pw_w);
    k_offsets<<<dim3(WW/32, HH/16, BB*GG), 256, OFF_SMEM_BYTES>>>(x, off_w, off_b);
    k_sample<<<dim3(NP / 8, GG), 256>>>(x);
    k_dwpw<<<dim3(WW/16, HH/8, BB*GG), 512, SM_BYTES>>>(
        dw_w, dw_b, pw_b, out);
}